// round 6
// baseline (speedup 1.0000x reference)
#include <cuda_runtime.h>

typedef unsigned long long ull;

#define D_DIM   128
#define K_DIM   32
#define N_PIX   4096
#define B_SZ    8
#define TILE_T  64
#define XSTRIDE 130   // x tile row stride (floats): conflict-free LDS.64 rows
#define CSTRIDE 132   // codeword row stride: float4-aligned, lh-pair quad-staggered
#define A2STRIDE 132  // duplicated-A row stride (floats): 64 ull + pad, quad-staggered

// shared-memory layout (float offsets)
#define X_OFF    0
#define C_OFF    (TILE_T * XSTRIDE)                  // 8320
#define A2_OFF   (C_OFF + K_DIM * CSTRIDE)           // 12544 (16B aligned)
#define XSQ_OFF  (A2_OFF + K_DIM * A2STRIDE)         // 16768
#define S_OFF    (XSQ_OFF + TILE_T)                  // 16832
#define BK_OFF   (S_OFF + K_DIM)                     // 16864
#define WAS_OFF  (BK_OFF + K_DIM)                    // 16896
#define ASUM_OFF (WAS_OFF + 8 * K_DIM)               // 17152
#define SMEM_FLOATS (ASUM_OFF + K_DIM)               // 17184
#define SMEM_BYTES  (SMEM_FLOATS * 4)                // 68736 B -> 3 blocks/SM

// packed fp32x2 FMA (Blackwell): acc.lo += a.lo*b.lo ; acc.hi += a.hi*b.hi
__device__ __forceinline__ void ffma2(ull &acc, ull a, ull b) {
    asm("fma.rn.f32x2 %0, %1, %2, %0;" : "+l"(acc) : "l"(a), "l"(b));
}
__device__ __forceinline__ float2 u2f(ull v) {
    float2 r;
    asm("mov.b64 {%0, %1}, %2;" : "=f"(r.x), "=f"(r.y) : "l"(v));
    return r;
}
__device__ __forceinline__ ull f2u(float x, float y) {
    ull v;
    asm("mov.b64 %0, {%1, %2};" : "=l"(v) : "f"(x), "f"(y));
    return v;
}

__global__ void zero_kernel(float4* p, int n4) {
    int i = blockIdx.x * blockDim.x + threadIdx.x;
    if (i < n4) p[i] = make_float4(0.f, 0.f, 0.f, 0.f);
}

// A-row permutation: logits/weights for codeword k live in A2 row r(k)
// r(k) = 2*(k&15) + (k>>4); inverse: row l holds k = (l>>1) + 16*(l&1)
__global__ void __launch_bounds__(256, 3)
enc_kernel(const float* __restrict__ X,
           const float* __restrict__ CW,
           const float* __restrict__ SC,
           float* __restrict__ out)
{
    extern __shared__ float sm[];

    const int tid  = threadIdx.x;
    const int w    = tid >> 5;
    const int l    = tid & 31;
    const int b    = blockIdx.x >> 6;      // batch (64 tiles per batch)
    const int tile = blockIdx.x & 63;
    const int n0   = tile * TILE_T;

    // ---- load X tile [128 d][64 t] into x_sh[t][XSTRIDE], codewords into c_sh ----
    {
        const float* Xb = X + (size_t)b * D_DIM * N_PIX + n0;
        #pragma unroll
        for (int s = 0; s < 32; s++) {
            int idx = tid + 256 * s;           // 0 .. 8191
            int d = idx >> 6;
            int t = idx & 63;
            sm[X_OFF + t * XSTRIDE + d] = Xb[d * N_PIX + t];
        }
        #pragma unroll
        for (int s = 0; s < 16; s++) {
            int idx = tid + 256 * s;           // 0 .. 4095
            int k = idx >> 7;
            int d = idx & 127;
            sm[C_OFF + k * CSTRIDE + d] = CW[idx];
        }
    }
    __syncthreads();

    // ---- xsq per pixel: warp w handles rows [w*8, w*8+8) ----
    #pragma unroll
    for (int p = 0; p < 8; p++) {
        int t = w * 8 + p;
        const float* row = sm + X_OFF + t * XSTRIDE;
        float2 v0 = *(const float2*)(row + 2 * l);
        float2 v1 = *(const float2*)(row + 64 + 2 * l);
        float ss = v0.x * v0.x + v0.y * v0.y + v1.x * v1.x + v1.y * v1.y;
        #pragma unroll
        for (int o = 16; o > 0; o >>= 1) ss += __shfl_xor_sync(0xffffffffu, ss, o);
        if (l == 0) sm[XSQ_OFF + t] = ss;
    }
    // ---- csq*scale and scale per codeword: warp w handles k = 4w..4w+3 ----
    #pragma unroll
    for (int jj = 0; jj < 4; jj++) {
        int k = 4 * w + jj;
        const float* row = sm + C_OFF + k * CSTRIDE;
        float2 v0 = *(const float2*)(row + 2 * l);
        float2 v1 = *(const float2*)(row + 64 + 2 * l);
        float ss = v0.x * v0.x + v0.y * v0.y + v1.x * v1.x + v1.y * v1.y;
        #pragma unroll
        for (int o = 16; o > 0; o >>= 1) ss += __shfl_xor_sync(0xffffffffu, ss, o);
        if (l == 0) {
            float sc = SC[k];
            sm[S_OFF + k]  = sc;
            sm[BK_OFF + k] = ss * sc;
        }
    }
    __syncthreads();

    // ---- Stage A: cross GEMM. Thread tile 2t x 4k, acc packed over d-pairs ----
    // warps: ko = w>>1 (k-octet), th = w&1 (t-half). lanes: lt = l&15, lh = l>>4.
    // t = 32*th + lt (+16);  k = 8*ko + lh + 2*j, j<4.
    // x loads: LDS.64, 16 distinct addrs (lh dup) -> 1 wf.
    // c loads: LDS.128 covering 4 d, 2 distinct addrs (lh) quad-staggered -> 1 wf.
    {
        const int lt = l & 15;
        const int lh = l >> 4;
        const int ko = w >> 1;
        const int th = w & 1;
        const int t0 = 32 * th + lt;
        const int kb = 8 * ko + lh;

        ull acc[8];                            // acc[i*4+j], i: t slot, j: k slot
        #pragma unroll
        for (int z = 0; z < 8; z++) acc[z] = 0ULL;

        const float* xr = sm + X_OFF + t0 * XSTRIDE;
        const float* cr = sm + C_OFF + kb * CSTRIDE;

        #pragma unroll 2
        for (int dq = 0; dq < 32; dq++) {
            int d4 = 4 * dq;
            ull xv00 = *(const ull*)(xr + d4);
            ull xv01 = *(const ull*)(xr + d4 + 2);
            ull xv10 = *(const ull*)(xr + 16 * XSTRIDE + d4);
            ull xv11 = *(const ull*)(xr + 16 * XSTRIDE + d4 + 2);
            ulonglong2 c0 = *(const ulonglong2*)(cr + 0 * 2 * CSTRIDE + d4);
            ulonglong2 c1 = *(const ulonglong2*)(cr + 1 * 2 * CSTRIDE + d4);
            ulonglong2 c2 = *(const ulonglong2*)(cr + 2 * 2 * CSTRIDE + d4);
            ulonglong2 c3 = *(const ulonglong2*)(cr + 3 * 2 * CSTRIDE + d4);
            ffma2(acc[0], xv00, c0.x); ffma2(acc[0], xv01, c0.y);
            ffma2(acc[1], xv00, c1.x); ffma2(acc[1], xv01, c1.y);
            ffma2(acc[2], xv00, c2.x); ffma2(acc[2], xv01, c2.y);
            ffma2(acc[3], xv00, c3.x); ffma2(acc[3], xv01, c3.y);
            ffma2(acc[4], xv10, c0.x); ffma2(acc[4], xv11, c0.y);
            ffma2(acc[5], xv10, c1.x); ffma2(acc[5], xv11, c1.y);
            ffma2(acc[6], xv10, c2.x); ffma2(acc[6], xv11, c2.y);
            ffma2(acc[7], xv10, c3.x); ffma2(acc[7], xv11, c3.y);
        }

        // logits -> A2 (duplicated (lg,lg) per ull slot), permuted row r(k)
        #pragma unroll
        for (int i = 0; i < 2; i++) {
            int t = t0 + 16 * i;
            float xsq = sm[XSQ_OFF + t];
            #pragma unroll
            for (int j = 0; j < 4; j++) {
                int k = kb + 2 * j;
                int r = 2 * (k & 15) + (k >> 4);
                float2 pr = u2f(acc[i * 4 + j]);
                float cross = pr.x + pr.y;
                float lg = fmaf(sm[S_OFF + k], fmaf(-2.0f, cross, xsq), sm[BK_OFF + k]);
                *(ull*)(sm + A2_OFF + r * A2STRIDE + 2 * t) = f2u(lg, lg);
            }
        }
    }
    __syncthreads();

    // ---- Softmax over k (lane l = row l = codeword (l>>1)+16*(l&1)) ----
    // No max pass: |logit| <= ~45, exp stays finite in fp32.
    {
        float asum_l = 0.0f;
        float* Arow = sm + A2_OFF + l * A2STRIDE;
        #pragma unroll
        for (int q2 = 0; q2 < 2; q2++) {
            int t0 = w * 8 + 4 * q2;
            float4 v0 = *(const float4*)(Arow + 2 * t0);       // t0 (x=y), t0+1 (z=w)
            float4 v1 = *(const float4*)(Arow + 2 * t0 + 4);   // t0+2, t0+3
            float e0 = __expf(v0.x), e1 = __expf(v0.z);
            float e2 = __expf(v1.x), e3 = __expf(v1.z);
            float s0 = e0, s1 = e1, s2 = e2, s3 = e3;
            #pragma unroll
            for (int o = 16; o > 0; o >>= 1) {
                s0 += __shfl_xor_sync(0xffffffffu, s0, o);
                s1 += __shfl_xor_sync(0xffffffffu, s1, o);
                s2 += __shfl_xor_sync(0xffffffffu, s2, o);
                s3 += __shfl_xor_sync(0xffffffffu, s3, o);
            }
            float a0 = e0 * __fdividef(1.0f, s0);
            float a1 = e1 * __fdividef(1.0f, s1);
            float a2 = e2 * __fdividef(1.0f, s2);
            float a3 = e3 * __fdividef(1.0f, s3);
            *(ull*)(Arow + 2 * t0 + 0) = f2u(a0, a0);
            *(ull*)(Arow + 2 * t0 + 2) = f2u(a1, a1);
            *(ull*)(Arow + 2 * t0 + 4) = f2u(a2, a2);
            *(ull*)(Arow + 2 * t0 + 6) = f2u(a3, a3);
            asum_l += a0 + a1 + a2 + a3;
        }
        sm[WAS_OFF + w * 32 + l] = asum_l;
    }
    __syncthreads();
    if (tid < 32) {
        float a = 0.0f;
        #pragma unroll
        for (int ww = 0; ww < 8; ww++) a += sm[WAS_OFF + ww * 32 + tid];
        int k = (tid >> 1) + 16 * (tid & 1);   // row tid holds codeword k
        sm[ASUM_OFF + k] = a;
    }
    __syncthreads();

    // ---- Stage B: E[k][d] += sum_t A[k][t] * x[t][d] ----
    // lanes: ld = l&15 (d-pair), lh = l>>4 (k-half). warps: dgrp = w&3, th = w>>2.
    // thread: d = 32*dgrp + 2*ld (+1), k = j + 16*lh (row 2j+lh), 32 t (th half).
    // A loads: ulonglong2 of duplicated pairs, 2 addrs (lh) quad-staggered -> 1 wf.
    {
        const int ld   = l & 15;
        const int lh   = l >> 4;
        const int dgrp = w & 3;
        const int th   = w >> 2;
        const int d0   = 32 * dgrp + 2 * ld;

        ull acc2[16];
        #pragma unroll
        for (int j = 0; j < 16; j++) acc2[j] = 0ULL;

        const float* xcol = sm + X_OFF + d0;
        const float* A2p  = sm + A2_OFF + lh * A2STRIDE;   // row 2j+lh

        #pragma unroll 1
        for (int q = 0; q < 8; q++) {           // 8 quads = 32 pixels (this half)
            int t = 32 * th + 4 * q;
            ull xv0 = *(const ull*)(xcol + (t + 0) * XSTRIDE);
            ull xv1 = *(const ull*)(xcol + (t + 1) * XSTRIDE);
            ull xv2 = *(const ull*)(xcol + (t + 2) * XSTRIDE);
            ull xv3 = *(const ull*)(xcol + (t + 3) * XSTRIDE);
            #pragma unroll
            for (int j = 0; j < 16; j++) {
                const float* Ar = A2p + 2 * j * A2STRIDE + 2 * t;
                ulonglong2 a01 = *(const ulonglong2*)(Ar);       // (a_t,a_t),(a_t+1,a_t+1)
                ulonglong2 a23 = *(const ulonglong2*)(Ar + 4);
                ffma2(acc2[j], a01.x, xv0);
                ffma2(acc2[j], a01.y, xv1);
                ffma2(acc2[j], a23.x, xv2);
                ffma2(acc2[j], a23.y, xv3);
            }
        }

        // fold -Asum[k]*c[k][d] once (th==0 half) and merge across blocks
        float* Eb = out + (size_t)b * K_DIM * D_DIM;
        #pragma unroll
        for (int j = 0; j < 16; j++) {
            int k = j + 16 * lh;
            float2 pr = u2f(acc2[j]);
            if (th == 0) {
                float as = sm[ASUM_OFF + k];
                pr.x = fmaf(-as, sm[C_OFF + k * CSTRIDE + d0],     pr.x);
                pr.y = fmaf(-as, sm[C_OFF + k * CSTRIDE + d0 + 1], pr.y);
            }
            atomicAdd(Eb + k * D_DIM + d0,     pr.x);
            atomicAdd(Eb + k * D_DIM + d0 + 1, pr.y);
        }
    }
}

extern "C" void kernel_launch(void* const* d_in, const int* in_sizes, int n_in,
                              void* d_out, int out_size)
{
    const float* X  = (const float*)d_in[0];
    const float* CW = (const float*)d_in[1];
    const float* SC = (const float*)d_in[2];
    float* out = (float*)d_out;

    cudaFuncSetAttribute(enc_kernel, cudaFuncAttributeMaxDynamicSharedMemorySize, SMEM_BYTES);

    const int OUT_N4 = (B_SZ * K_DIM * D_DIM) / 4;      // 8192 float4
    zero_kernel<<<OUT_N4 / 256, 256>>>((float4*)out, OUT_N4);
    enc_kernel<<<B_SZ * (N_PIX / TILE_T), 256, SMEM_BYTES>>>(X, CW, SC, out);
}

// round 7
// speedup vs baseline: 1.1977x; 1.1977x over previous
#include <cuda_runtime.h>

typedef unsigned long long ull;

#define D_DIM   128
#define K_DIM   32
#define N_PIX   4096
#define B_SZ    8
#define TILE_T  128
#define XSTRIDE 130   // x row stride: conflict-free LDS.64 rows (stage A) + LDS.32/64 columns (stage B)
#define CSTRIDE 132   // codeword row stride: 16B-aligned, lh row-pair quad-staggered for ulonglong2 loads
#define ASTRIDE 132   // A row stride: 16B-aligned rows for float4 softmax/stage-B reads

// shared-memory layout (float offsets)
#define X_OFF    0
#define C_OFF    (TILE_T * XSTRIDE)                  // 16640
#define A_OFF    (C_OFF + K_DIM * CSTRIDE)           // 20864 (16B aligned)
#define XSQ_OFF  (A_OFF + K_DIM * ASTRIDE)           // 25088
#define S_OFF    (XSQ_OFF + TILE_T)                  // 25216
#define BK_OFF   (S_OFF + K_DIM)                     // 25248
#define WAS_OFF  (BK_OFF + K_DIM)                    // 25280
#define ASUM_OFF (WAS_OFF + 8 * K_DIM)               // 25536
#define SMEM_FLOATS (ASUM_OFF + K_DIM)               // 25568
#define SMEM_BYTES  (SMEM_FLOATS * 4)                // 102272 B -> 2 blocks/SM, single wave at grid=256

// packed fp32x2 FMA (Blackwell): acc.lo += a.lo*b.lo ; acc.hi += a.hi*b.hi
__device__ __forceinline__ void ffma2(ull &acc, ull a, ull b) {
    asm("fma.rn.f32x2 %0, %1, %2, %0;" : "+l"(acc) : "l"(a), "l"(b));
}
__device__ __forceinline__ float2 u2f(ull v) {
    float2 r;
    asm("mov.b64 {%0, %1}, %2;" : "=f"(r.x), "=f"(r.y) : "l"(v));
    return r;
}
__device__ __forceinline__ ull f2u(float x, float y) {
    ull v;
    asm("mov.b64 %0, {%1, %2};" : "=l"(v) : "f"(x), "f"(y));
    return v;
}

__global__ void zero_kernel(float4* p, int n4) {
    int i = blockIdx.x * blockDim.x + threadIdx.x;
    if (i < n4) p[i] = make_float4(0.f, 0.f, 0.f, 0.f);
}

__global__ void __launch_bounds__(256, 2)
enc_kernel(const float* __restrict__ X,
           const float* __restrict__ CW,
           const float* __restrict__ SC,
           float* __restrict__ out)
{
    extern __shared__ float sm[];

    const int tid  = threadIdx.x;
    const int w    = tid >> 5;
    const int l    = tid & 31;
    const int b    = blockIdx.x >> 5;      // batch (32 tiles per batch)
    const int tile = blockIdx.x & 31;
    const int n0   = tile * TILE_T;

    // ---- load X tile [128 d][128 t] into x_sh[t][XSTRIDE], codewords into c_sh ----
    {
        const float* Xb = X + (size_t)b * D_DIM * N_PIX + n0;
        #pragma unroll
        for (int s = 0; s < 64; s++) {
            int idx = tid + 256 * s;           // 0 .. 16383
            int d = idx >> 7;
            int t = idx & 127;
            sm[X_OFF + t * XSTRIDE + d] = Xb[d * N_PIX + t];
        }
        #pragma unroll
        for (int s = 0; s < 16; s++) {
            int idx = tid + 256 * s;           // 0 .. 4095
            int k = idx >> 7;
            int d = idx & 127;
            sm[C_OFF + k * CSTRIDE + d] = CW[idx];
        }
    }
    __syncthreads();

    // ---- xsq per pixel: warp w handles rows [w*16, w*16+16) ----
    #pragma unroll
    for (int p = 0; p < 16; p++) {
        int t = w * 16 + p;
        const float* row = sm + X_OFF + t * XSTRIDE;
        float2 v0 = *(const float2*)(row + 2 * l);
        float2 v1 = *(const float2*)(row + 64 + 2 * l);
        float ss = v0.x * v0.x + v0.y * v0.y + v1.x * v1.x + v1.y * v1.y;
        #pragma unroll
        for (int o = 16; o > 0; o >>= 1) ss += __shfl_xor_sync(0xffffffffu, ss, o);
        if (l == 0) sm[XSQ_OFF + t] = ss;
    }
    // ---- csq*scale and scale per codeword: warp w handles k = 4w..4w+3 ----
    #pragma unroll
    for (int jj = 0; jj < 4; jj++) {
        int k = 4 * w + jj;
        const float* row = sm + C_OFF + k * CSTRIDE;
        float2 v0 = *(const float2*)(row + 2 * l);
        float2 v1 = *(const float2*)(row + 64 + 2 * l);
        float ss = v0.x * v0.x + v0.y * v0.y + v1.x * v1.x + v1.y * v1.y;
        #pragma unroll
        for (int o = 16; o > 0; o >>= 1) ss += __shfl_xor_sync(0xffffffffu, ss, o);
        if (l == 0) {
            float sc = SC[k];
            sm[S_OFF + k]  = sc;
            sm[BK_OFF + k] = ss * sc;
        }
    }
    __syncthreads();

    // ---- Stage A: cross GEMM. Thread tile 4t x 4k, acc packed over d-pairs ----
    // warps: ko = w>>1 (k-octet), th = w&1 (t-half of 64). lanes: lt = l&15, lh = l>>4.
    // t_i = 64*th + lt + 16*i (i<4);  k_j = 8*ko + lh + 2*j (j<4).
    // x loads: LDS.64, 16 distinct addrs (lh dup) -> 1 wf each (8 per dq).
    // c loads: LDS.128 over 4 d, 2 distinct addrs (lh rows, quad-staggered) -> 1 wf each (4 per dq).
    // 12 wf / 32 FFMA2 per dq.
    {
        const int lt = l & 15;
        const int lh = l >> 4;
        const int ko = w >> 1;
        const int th = w & 1;
        const int kb = 8 * ko + lh;

        ull acc[16];
        #pragma unroll
        for (int z = 0; z < 16; z++) acc[z] = 0ULL;

        const float* xr = sm + X_OFF + (64 * th + lt) * XSTRIDE;
        const float* cr = sm + C_OFF + kb * CSTRIDE;

        #pragma unroll 2
        for (int dq = 0; dq < 32; dq++) {
            int d4 = 4 * dq;
            ull xv[4][2];
            #pragma unroll
            for (int i = 0; i < 4; i++) {
                xv[i][0] = *(const ull*)(xr + i * 16 * XSTRIDE + d4);
                xv[i][1] = *(const ull*)(xr + i * 16 * XSTRIDE + d4 + 2);
            }
            ulonglong2 c0 = *(const ulonglong2*)(cr + 0 * 2 * CSTRIDE + d4);
            ulonglong2 c1 = *(const ulonglong2*)(cr + 1 * 2 * CSTRIDE + d4);
            ulonglong2 c2 = *(const ulonglong2*)(cr + 2 * 2 * CSTRIDE + d4);
            ulonglong2 c3 = *(const ulonglong2*)(cr + 3 * 2 * CSTRIDE + d4);
            #pragma unroll
            for (int i = 0; i < 4; i++) {
                ffma2(acc[i * 4 + 0], xv[i][0], c0.x); ffma2(acc[i * 4 + 0], xv[i][1], c0.y);
                ffma2(acc[i * 4 + 1], xv[i][0], c1.x); ffma2(acc[i * 4 + 1], xv[i][1], c1.y);
                ffma2(acc[i * 4 + 2], xv[i][0], c2.x); ffma2(acc[i * 4 + 2], xv[i][1], c2.y);
                ffma2(acc[i * 4 + 3], xv[i][0], c3.x); ffma2(acc[i * 4 + 3], xv[i][1], c3.y);
            }
        }

        // logits = scale_k*(xsq - 2*cross) + csq_k*scale_k -> A[k][t]
        #pragma unroll
        for (int i = 0; i < 4; i++) {
            int t = 64 * th + lt + 16 * i;
            float xsq = sm[XSQ_OFF + t];
            #pragma unroll
            for (int j = 0; j < 4; j++) {
                int k = kb + 2 * j;
                float2 pr = u2f(acc[i * 4 + j]);
                float cross = pr.x + pr.y;
                float lg = fmaf(sm[S_OFF + k], fmaf(-2.0f, cross, xsq), sm[BK_OFF + k]);
                sm[A_OFF + k * ASTRIDE + t] = lg;
            }
        }
    }
    __syncthreads();

    // ---- Softmax over k (lane = k): warp w handles px [16w,16w+16), float4 rows ----
    // No max pass: |logit| bounded (~45), exp stays finite in fp32.
    {
        float asum_l = 0.0f;
        float* Arow = sm + A_OFF + l * ASTRIDE;
        #pragma unroll
        for (int q = 0; q < 4; q++) {
            int t0 = w * 16 + 4 * q;
            float4 v = *(const float4*)(Arow + t0);
            float e0 = __expf(v.x), e1 = __expf(v.y);
            float e2 = __expf(v.z), e3 = __expf(v.w);
            float s0 = e0, s1 = e1, s2 = e2, s3 = e3;
            #pragma unroll
            for (int o = 16; o > 0; o >>= 1) {
                s0 += __shfl_xor_sync(0xffffffffu, s0, o);
                s1 += __shfl_xor_sync(0xffffffffu, s1, o);
                s2 += __shfl_xor_sync(0xffffffffu, s2, o);
                s3 += __shfl_xor_sync(0xffffffffu, s3, o);
            }
            float a0 = e0 * __fdividef(1.0f, s0);
            float a1 = e1 * __fdividef(1.0f, s1);
            float a2 = e2 * __fdividef(1.0f, s2);
            float a3 = e3 * __fdividef(1.0f, s3);
            *(float4*)(Arow + t0) = make_float4(a0, a1, a2, a3);
            asum_l += a0 + a1 + a2 + a3;
        }
        sm[WAS_OFF + w * 32 + l] = asum_l;
    }
    __syncthreads();
    if (tid < 32) {
        float a = 0.0f;
        #pragma unroll
        for (int ww = 0; ww < 8; ww++) a += sm[WAS_OFF + ww * 32 + tid];
        sm[ASUM_OFF + tid] = a;
    }
    __syncthreads();

    // ---- Stage B: E[k][d] += sum_t A[k][t] * x[t][d], pixel-pair packed ----
    {
        const int g = tid >> 7;        // pixel half: [0,64) or [64,128)
        const int d = tid & 127;

        ull acc2[32];
        #pragma unroll
        for (int k = 0; k < 32; k++) acc2[k] = 0ULL;

        const float* xcol = sm + X_OFF + d;
        const int tbase = g * 64;

        #pragma unroll 2
        for (int q = 0; q < 16; q++) {          // 16 quads = 64 pixels (this half)
            int t = tbase + q * 4;
            float x0 = xcol[(t + 0) * XSTRIDE];
            float x1 = xcol[(t + 1) * XSTRIDE];
            float x2 = xcol[(t + 2) * XSTRIDE];
            float x3 = xcol[(t + 3) * XSTRIDE];
            ull xv01 = f2u(x0, x1);
            ull xv23 = f2u(x2, x3);
            const float* Ab = sm + A_OFF + t;
            #pragma unroll
            for (int k = 0; k < 32; k++) {
                float4 a = *(const float4*)(Ab + k * ASTRIDE);   // broadcast LDS.128
                ffma2(acc2[k], f2u(a.x, a.y), xv01);
                ffma2(acc2[k], f2u(a.z, a.w), xv23);
            }
        }

        // fold -Asum[k]*c[k][d] once (group 0 only) and merge across blocks
        float* Eb = out + (size_t)b * K_DIM * D_DIM + d;
        #pragma unroll
        for (int k = 0; k < 32; k++) {
            float2 pr = u2f(acc2[k]);
            float v = pr.x + pr.y;
            if (g == 0) v = fmaf(-sm[ASUM_OFF + k], sm[C_OFF + k * CSTRIDE + d], v);
            atomicAdd(Eb + k * D_DIM, v);
        }
    }
}

extern "C" void kernel_launch(void* const* d_in, const int* in_sizes, int n_in,
                              void* d_out, int out_size)
{
    const float* X  = (const float*)d_in[0];
    const float* CW = (const float*)d_in[1];
    const float* SC = (const float*)d_in[2];
    float* out = (float*)d_out;

    cudaFuncSetAttribute(enc_kernel, cudaFuncAttributeMaxDynamicSharedMemorySize, SMEM_BYTES);

    const int OUT_N4 = (B_SZ * K_DIM * D_DIM) / 4;      // 8192 float4
    zero_kernel<<<OUT_N4 / 256, 256>>>((float4*)out, OUT_N4);
    enc_kernel<<<B_SZ * (N_PIX / TILE_T), 256, SMEM_BYTES>>>(X, CW, SC, out);
}

// round 8
// speedup vs baseline: 1.6259x; 1.3574x over previous
#include <cuda_runtime.h>

typedef unsigned long long ull;

#define D_DIM   128
#define K_DIM   32
#define N_PIX   4096
#define B_SZ    8
#define TILE_T  128
#define XSTRIDE 130   // x row stride: even (ull-aligned), conflict-free lane patterns used below
#define CSTRIDE 132   // codeword row stride
#define ASTRIDE 34    // A / Ered row stride in floats (17 ulls)

// shared-memory layout (float offsets)
#define X_OFF    0
#define C_OFF    (TILE_T * XSTRIDE)                  // 16640
#define A_OFF    (C_OFF + K_DIM * CSTRIDE)           // 20864 (ull aligned)
#define XSQ_OFF  (A_OFF + TILE_T * ASTRIDE)          // 25216
#define XSP_OFF  (XSQ_OFF + TILE_T)                  // 25344 (2 x 128 partials)
#define S_OFF    (XSP_OFF + 2 * TILE_T)              // 25600
#define BK_OFF   (S_OFF + K_DIM)                     // 25632
#define WAS_OFF  (BK_OFF + K_DIM)                    // 25664
#define ASUM_OFF (WAS_OFF + 8 * K_DIM)               // 25920
#define SMEM_FLOATS (ASUM_OFF + K_DIM)               // 25952
#define SMEM_BYTES  (SMEM_FLOATS * 4)                // 103808 B -> 2 blocks/SM, single wave @ grid 256

// packed fp32x2 FMA (Blackwell): acc.lo += a.lo*b.lo ; acc.hi += a.hi*b.hi
__device__ __forceinline__ void ffma2(ull &acc, ull a, ull b) {
    asm("fma.rn.f32x2 %0, %1, %2, %0;" : "+l"(acc) : "l"(a), "l"(b));
}
__device__ __forceinline__ float2 u2f(ull v) {
    float2 r;
    asm("mov.b64 {%0, %1}, %2;" : "=f"(r.x), "=f"(r.y) : "l"(v));
    return r;
}
__device__ __forceinline__ ull f2u(float x, float y) {
    ull v;
    asm("mov.b64 %0, {%1, %2};" : "=l"(v) : "f"(x), "f"(y));
    return v;
}

__global__ void zero_kernel(float4* p, int n4) {
    int i = blockIdx.x * blockDim.x + threadIdx.x;
    if (i < n4) p[i] = make_float4(0.f, 0.f, 0.f, 0.f);
}

__global__ void __launch_bounds__(256, 2)
enc_kernel(const float* __restrict__ X,
           const float* __restrict__ CW,
           const float* __restrict__ SC,
           float* __restrict__ out)
{
    extern __shared__ float sm[];

    const int tid  = threadIdx.x;
    const int w    = tid >> 5;
    const int l    = tid & 31;
    const int b    = blockIdx.x >> 5;      // batch (32 tiles per batch)
    const int tile = blockIdx.x & 31;
    const int n0   = tile * TILE_T;

    // ---- load X tile [128 d][128 t] -> x_sh[t][130], folding per-pixel x^2 partials ----
    // thread: t = tid&127 (fixed), d = (tid>>7) + 2*s  -> each thread owns 64 d's of one pixel.
    {
        const float* Xb = X + (size_t)b * D_DIM * N_PIX + n0;
        const int tl = tid & 127;
        const int dh = tid >> 7;
        float ssq = 0.0f;
        #pragma unroll 8
        for (int s = 0; s < 64; s++) {
            int d = dh + 2 * s;
            float v = Xb[(size_t)d * N_PIX + tl];
            sm[X_OFF + tl * XSTRIDE + d] = v;
            ssq = fmaf(v, v, ssq);
        }
        sm[XSP_OFF + dh * TILE_T + tl] = ssq;

        #pragma unroll
        for (int s = 0; s < 16; s++) {
            int idx = tid + 256 * s;           // 0..4095
            int k = idx >> 7;
            int d = idx & 127;
            sm[C_OFF + k * CSTRIDE + d] = CW[idx];
        }
    }
    __syncthreads();

    // ---- finalize xsq; csq*scale per codeword ----
    if (tid < TILE_T)
        sm[XSQ_OFF + tid] = sm[XSP_OFF + tid] + sm[XSP_OFF + TILE_T + tid];
    #pragma unroll
    for (int jj = 0; jj < 4; jj++) {
        int k = 4 * w + jj;
        const float* row = sm + C_OFF + k * CSTRIDE;
        float2 v0 = *(const float2*)(row + 2 * l);
        float2 v1 = *(const float2*)(row + 64 + 2 * l);
        float ss = v0.x * v0.x + v0.y * v0.y + v1.x * v1.x + v1.y * v1.y;
        #pragma unroll
        for (int o = 16; o > 0; o >>= 1) ss += __shfl_xor_sync(0xffffffffu, ss, o);
        if (l == 0) {
            float sc = SC[k];
            sm[S_OFF + k]  = sc;
            sm[BK_OFF + k] = ss * sc;
        }
    }
    __syncthreads();

    // ---- Stage A: cross[t][k] = sum_d x[t][d]*c[k][d]; 8t x 4k tile, d-pair acc, 2-way d split ----
    // g = w>>2 (d-half 64), lanes: tb = l&15, lh = l>>4; kb = 2*(w&3)+lh in [0,8); k = 4kb+jj.
    // t = tb + 16*i. x: LDS.64, 16 distinct bank-pairs (65*tb mod 16 = tb) conflict-free.
    const int g  = w >> 2;
    const int tb = l & 15;
    const int lh = l >> 4;
    {
        const int kb = 2 * (w & 3) + lh;

        ull acc[8][4];
        #pragma unroll
        for (int i = 0; i < 8; i++)
            #pragma unroll
            for (int jj = 0; jj < 4; jj++) acc[i][jj] = 0ULL;

        const float* xr = sm + X_OFF + tb * XSTRIDE + 64 * g;
        const float* cr = sm + C_OFF + (4 * kb) * CSTRIDE + 64 * g;

        #pragma unroll 2
        for (int dp = 0; dp < 32; dp++) {
            ull cv[4];
            #pragma unroll
            for (int jj = 0; jj < 4; jj++)
                cv[jj] = *(const ull*)(cr + jj * CSTRIDE + 2 * dp);
            #pragma unroll
            for (int i = 0; i < 8; i++) {
                ull xv = *(const ull*)(xr + (16 * i) * XSTRIDE + 2 * dp);
                ffma2(acc[i][0], xv, cv[0]);
                ffma2(acc[i][1], xv, cv[1]);
                ffma2(acc[i][2], xv, cv[2]);
                ffma2(acc[i][3], xv, cv[3]);
            }
        }

        // g==1 writes partial cross pairs (k,k+1) into A[t][k] (float offset = k)
        if (g == 1) {
            #pragma unroll
            for (int i = 0; i < 8; i++) {
                int t = tb + 16 * i;
                #pragma unroll
                for (int jp = 0; jp < 2; jp++) {
                    float2 p0 = u2f(acc[i][2 * jp]);
                    float2 p1 = u2f(acc[i][2 * jp + 1]);
                    *(ull*)(sm + A_OFF + t * ASTRIDE + 4 * kb + 2 * jp) =
                        f2u(p0.x + p0.y, p1.x + p1.y);
                }
            }
        }
        __syncthreads();
        // g==0 adds its partial, computes logits, writes back in place
        if (g == 0) {
            float sv[4], bv[4];
            #pragma unroll
            for (int jj = 0; jj < 4; jj++) {
                sv[jj] = sm[S_OFF + 4 * kb + jj];
                bv[jj] = sm[BK_OFF + 4 * kb + jj];
            }
            #pragma unroll
            for (int i = 0; i < 8; i++) {
                int t = tb + 16 * i;
                float xsq = sm[XSQ_OFF + t];
                #pragma unroll
                for (int jp = 0; jp < 2; jp++) {
                    ull* addr = (ull*)(sm + A_OFF + t * ASTRIDE + 4 * kb + 2 * jp);
                    float2 oth = u2f(*addr);
                    float2 p0 = u2f(acc[i][2 * jp]);
                    float2 p1 = u2f(acc[i][2 * jp + 1]);
                    float cr0 = oth.x + p0.x + p0.y;
                    float cr1 = oth.y + p1.x + p1.y;
                    float lg0 = fmaf(sv[2 * jp],     fmaf(-2.0f, cr0, xsq), bv[2 * jp]);
                    float lg1 = fmaf(sv[2 * jp + 1], fmaf(-2.0f, cr1, xsq), bv[2 * jp + 1]);
                    *addr = f2u(lg0, lg1);
                }
            }
        }
    }
    __syncthreads();

    // ---- Softmax over k (lane = k): warp w handles px [16w, 16w+16); no max pass ----
    {
        float asum_l = 0.0f;
        #pragma unroll
        for (int q = 0; q < 4; q++) {
            int t0 = w * 16 + 4 * q;
            float v0 = sm[A_OFF + (t0 + 0) * ASTRIDE + l];
            float v1 = sm[A_OFF + (t0 + 1) * ASTRIDE + l];
            float v2 = sm[A_OFF + (t0 + 2) * ASTRIDE + l];
            float v3 = sm[A_OFF + (t0 + 3) * ASTRIDE + l];
            float e0 = __expf(v0), e1 = __expf(v1);
            float e2 = __expf(v2), e3 = __expf(v3);
            float s0 = e0, s1 = e1, s2 = e2, s3 = e3;
            #pragma unroll
            for (int o = 16; o > 0; o >>= 1) {
                s0 += __shfl_xor_sync(0xffffffffu, s0, o);
                s1 += __shfl_xor_sync(0xffffffffu, s1, o);
                s2 += __shfl_xor_sync(0xffffffffu, s2, o);
                s3 += __shfl_xor_sync(0xffffffffu, s3, o);
            }
            float a0 = e0 * __fdividef(1.0f, s0);
            float a1 = e1 * __fdividef(1.0f, s1);
            float a2 = e2 * __fdividef(1.0f, s2);
            float a3 = e3 * __fdividef(1.0f, s3);
            sm[A_OFF + (t0 + 0) * ASTRIDE + l] = a0;
            sm[A_OFF + (t0 + 1) * ASTRIDE + l] = a1;
            sm[A_OFF + (t0 + 2) * ASTRIDE + l] = a2;
            sm[A_OFF + (t0 + 3) * ASTRIDE + l] = a3;
            asum_l += a0 + a1 + a2 + a3;
        }
        sm[WAS_OFF + w * 32 + l] = asum_l;
    }
    __syncthreads();
    if (tid < 32) {
        float a = 0.0f;
        #pragma unroll
        for (int ww = 0; ww < 8; ww++) a += sm[WAS_OFF + ww * 32 + tid];
        sm[ASUM_OFF + tid] = a;
    }
    __syncthreads();

    // ---- Stage B: E[k][d] = sum_t A[k][t]*x[t][d]; 8k x 4d tile, k-pair acc, 2-way t split ----
    // gB = w>>2 (t-half), kbB = w&3 (k-octet, uniform per warp), db = l; d = db + 32*j.
    // A loads: native ull pairs (A[t][k],A[t][k+1]) from t-major rows, uniform per warp.
    {
        const int gB  = w >> 2;
        const int kbB = w & 3;
        const int db  = l;

        ull acc2[4][4];
        #pragma unroll
        for (int jj = 0; jj < 4; jj++)
            #pragma unroll
            for (int j = 0; j < 4; j++) acc2[jj][j] = 0ULL;

        const int t0 = 64 * gB;
        #pragma unroll 2
        for (int tt = 0; tt < 64; tt++) {
            int t = t0 + tt;
            const float* xrow = sm + X_OFF + t * XSTRIDE + db;
            ull xx[4];
            #pragma unroll
            for (int j = 0; j < 4; j++) {
                float xv = xrow[32 * j];
                xx[j] = f2u(xv, xv);
            }
            const float* Ar = sm + A_OFF + t * ASTRIDE + 8 * kbB;
            ull av0 = *(const ull*)(Ar + 0);
            ull av1 = *(const ull*)(Ar + 2);
            ull av2 = *(const ull*)(Ar + 4);
            ull av3 = *(const ull*)(Ar + 6);
            #pragma unroll
            for (int j = 0; j < 4; j++) {
                ffma2(acc2[0][j], av0, xx[j]);
                ffma2(acc2[1][j], av1, xx[j]);
                ffma2(acc2[2][j], av2, xx[j]);
                ffma2(acc2[3][j], av3, xx[j]);
            }
        }
        __syncthreads();           // all A reads done; A region becomes Ered[d][k]

        if (gB == 0) {             // write partials: Ered row d, float offset = k
            #pragma unroll
            for (int jj = 0; jj < 4; jj++)
                #pragma unroll
                for (int j = 0; j < 4; j++) {
                    int d = db + 32 * j;
                    *(ull*)(sm + A_OFF + d * ASTRIDE + 8 * kbB + 2 * jj) = acc2[jj][j];
                }
        }
        __syncthreads();
        if (gB == 1) {             // add own partial, fold -asum*c, atomic merge
            float* Eb = out + (size_t)b * K_DIM * D_DIM;
            #pragma unroll
            for (int jj = 0; jj < 4; jj++) {
                int k0 = 8 * kbB + 2 * jj;
                float as0 = sm[ASUM_OFF + k0];
                float as1 = sm[ASUM_OFF + k0 + 1];
                #pragma unroll
                for (int j = 0; j < 4; j++) {
                    int d = db + 32 * j;
                    float2 mine = u2f(acc2[jj][j]);
                    float2 oth  = u2f(*(const ull*)(sm + A_OFF + d * ASTRIDE + k0));
                    float v0 = fmaf(-as0, sm[C_OFF + k0 * CSTRIDE + d],       mine.x + oth.x);
                    float v1 = fmaf(-as1, sm[C_OFF + (k0 + 1) * CSTRIDE + d], mine.y + oth.y);
                    atomicAdd(Eb + k0 * D_DIM + d,           v0);
                    atomicAdd(Eb + (k0 + 1) * D_DIM + d,     v1);
                }
            }
        }
    }
}

extern "C" void kernel_launch(void* const* d_in, const int* in_sizes, int n_in,
                              void* d_out, int out_size)
{
    const float* X  = (const float*)d_in[0];
    const float* CW = (const float*)d_in[1];
    const float* SC = (const float*)d_in[2];
    float* out = (float*)d_out;

    cudaFuncSetAttribute(enc_kernel, cudaFuncAttributeMaxDynamicSharedMemorySize, SMEM_BYTES);

    const int OUT_N4 = (B_SZ * K_DIM * D_DIM) / 4;      // 8192 float4
    zero_kernel<<<OUT_N4 / 256, 256>>>((float4*)out, OUT_N4);
    enc_kernel<<<B_SZ * (N_PIX / TILE_T), 256, SMEM_BYTES>>>(X, CW, SC, out);
}